// round 16
// baseline (speedup 1.0000x reference)
#include <cuda_runtime.h>
#include <cuda_fp16.h>
#include <cstdint>

// ---------------------------------------------------------------------------
// Problem constants
// ---------------------------------------------------------------------------
#define NB 64
#define LL 512
#define SS 16
#define HH 768
#define M_TOTAL (NB * LL)          // 32768

#define PASS_OFF 0
#define SENT_OFF (NB * HH)
#define MASK_OFF (NB * HH + NB * SS * HH)
#define OUT_TOTAL (NB * HH + NB * SS * HH + NB * SS)   // 836608

// GEMM tiling: CTA 128x128, 4 warps of 64x64, BK=64, 3 stages, 1 barrier/kt
#define BM 128
#define BN 128
#define BK 64
#define NKCH (HH / BK)             // 12
#define NKS (BK / 16)              // 4 (even -> frag parity carries across kt)
#define ROWB 144                   // 64 halves (128B) padded to 144B
#define OFF_AH 0
#define OFF_BH (128 * ROWB)        // 18432
#define STAGE_B (2 * 128 * ROWB)   // 36864
#define NSTAGE 3
#define DYN_SMEM (NSTAGE * STAGE_B)   // 110592 -> 2 CTAs/SM (221KB)

// ---------------------------------------------------------------------------
// Device scratch
// ---------------------------------------------------------------------------
__device__ __half g_xh[(size_t)M_TOTAL * HH];      // 48 MB
__device__ __half g_wh[HH * HH];

// ---------------------------------------------------------------------------
// PTX helpers
// ---------------------------------------------------------------------------
__device__ __forceinline__ uint32_t smem_u32(const void* p) {
    uint32_t a;
    asm("{ .reg .u64 t; cvta.to.shared.u64 t, %1; cvt.u32.u64 %0, t; }"
        : "=r"(a) : "l"(p));
    return a;
}

__device__ __forceinline__ void cp16(uint32_t saddr, const void* g) {
    asm volatile("cp.async.cg.shared.global [%0], [%1], 16;"
                 :: "r"(saddr), "l"(g) : "memory");
}

#define CP_COMMIT() asm volatile("cp.async.commit_group;" ::: "memory")

#define LDSM_X4(r0, r1, r2, r3, addr) \
    asm volatile("ldmatrix.sync.aligned.m8n8.x4.shared.b16 {%0,%1,%2,%3}, [%4];" \
                 : "=r"(r0), "=r"(r1), "=r"(r2), "=r"(r3) : "r"(addr))

#define MMA16816(c, a, b0, b1) \
    asm volatile("mma.sync.aligned.m16n8k16.row.col.f32.f16.f16.f32 " \
                 "{%0,%1,%2,%3}, {%4,%5,%6,%7}, {%8,%9}, {%0,%1,%2,%3};" \
                 : "+f"((c)[0]), "+f"((c)[1]), "+f"((c)[2]), "+f"((c)[3]) \
                 : "r"((a)[0]), "r"((a)[1]), "r"((a)[2]), "r"((a)[3]), \
                   "r"(b0), "r"(b1))

__device__ __forceinline__ float tanh_fast(float x) {
    float y;
    asm("tanh.approx.f32 %0, %1;" : "=f"(y) : "f"(x));
    return y;
}

// ---------------------------------------------------------------------------
// convert_x (MLP=4) + convert_w + output zero-init, one launch
// ---------------------------------------------------------------------------
#define X4 ((size_t)M_TOTAL * HH / 4)          // 6291456 float4s
#define XBLK ((X4 + 1023) / 1024)              // 6144 blocks (4 float4/thread)
#define W4 ((size_t)HH * HH / 4)               // 147456
#define WBLK ((W4 + 255) / 256)                // 576
#define O4 (OUT_TOTAL / 4)                     // 209152
#define OBLK ((O4 + 255) / 256)                // 818

__global__ __launch_bounds__(256) void convert_init_kernel(
    const float* __restrict__ xsrc, const float* __restrict__ wsrc,
    float* __restrict__ out) {
    const size_t bx = blockIdx.x;
    if (bx < XBLK) {
        const size_t base = bx * 1024 + threadIdx.x;
        float4 v[4];
#pragma unroll
        for (int j = 0; j < 4; j++)
            v[j] = reinterpret_cast<const float4*>(xsrc)[base + j * 256];
#pragma unroll
        for (int j = 0; j < 4; j++) {
            const size_t i = base + j * 256;
            reinterpret_cast<__half2*>(g_xh)[2 * i] =
                __half2(__float2half_rn(v[j].x), __float2half_rn(v[j].y));
            reinterpret_cast<__half2*>(g_xh)[2 * i + 1] =
                __half2(__float2half_rn(v[j].z), __float2half_rn(v[j].w));
        }
    } else if (bx < XBLK + WBLK) {
        size_t i = (bx - XBLK) * 256 + threadIdx.x;
        if (i >= W4) return;
        float4 v = reinterpret_cast<const float4*>(wsrc)[i];
        reinterpret_cast<__half2*>(g_wh)[2 * i] =
            __half2(__float2half_rn(v.x), __float2half_rn(v.y));
        reinterpret_cast<__half2*>(g_wh)[2 * i + 1] =
            __half2(__float2half_rn(v.z), __float2half_rn(v.w));
    } else {
        size_t i = (bx - XBLK - WBLK) * 256 + threadIdx.x;
        if (i < O4)
            reinterpret_cast<float4*>(out)[i] = make_float4(0.f, 0.f, 0.f, 0.f);
    }
}

// ---------------------------------------------------------------------------
// GEMM + fused pooling epilogue. CTA 128x128, 4 warps 64x64, BK=64,
// 3-stage, 1 barrier/kt, spread refill, cross-kt fragment pipelining.
// ---------------------------------------------------------------------------
__device__ __forceinline__ void load_chunk(uint32_t sb, int k0, int m0, int n0,
                                           int chunk) {
    const int t = threadIdx.x;
#pragma unroll
    for (int i = 2 * chunk; i < 2 * chunk + 2; i++) {
        int c = t + 128 * i;
        int row = c >> 3, ch = c & 7;
        uint32_t so = (uint32_t)(row * ROWB + ch * 16);
        cp16(sb + OFF_AH + so, g_xh + (size_t)(m0 + row) * HH + k0 + ch * 8);
        cp16(sb + OFF_BH + so, g_wh + (size_t)(n0 + row) * HH + k0 + ch * 8);
    }
}

__device__ __forceinline__ void load_stage(uint32_t sb, int k0, int m0, int n0) {
#pragma unroll
    for (int ch = 0; ch < 4; ch++) load_chunk(sb, k0, m0, n0, ch);
    CP_COMMIT();
}

__global__ __launch_bounds__(128, 2) void gemm_kernel(
    const float* __restrict__ bias,
    const int* __restrict__ spans,
    float* __restrict__ out)
{
    extern __shared__ char dsm[];
    __shared__ float s_bias[BN];
    __shared__ int   s_sp[SS * 2];
    __shared__ float s_inv[SS];

    const int tid = threadIdx.x;
    const int wid = tid >> 5;
    const int lane = tid & 31;
    const int m0 = blockIdx.y * BM;
    const int n0 = blockIdx.x * BN;
    const int nidx = m0 >> 9;
    const int ltile = m0 & 511;

    const int mw = (wid & 1) * 64;
    const int nw = (wid >> 1) * 64;

    const uint32_t sbase = smem_u32(dsm);

    s_bias[tid] = bias[n0 + tid];
    if (tid < SS * 2) s_sp[tid] = spans[nidx * SS * 2 + tid];
    if (tid >= 64 && tid < 64 + SS) {
        int s = tid - 64;
        int st = spans[(nidx * SS + s) * 2];
        int en = spans[(nidx * SS + s) * 2 + 1];
        s_inv[s] = 1.0f / (float)(en - st);
    }

    float c[4][8][4];
#pragma unroll
    for (int mt = 0; mt < 4; mt++)
#pragma unroll
        for (int j = 0; j < 8; j++)
#pragma unroll
            for (int r = 0; r < 4; r++) c[mt][j][r] = 0.0f;

    const uint32_t a_row = (uint32_t)(mw + (lane & 15)) * ROWB;
    const uint32_t a_col = ((lane >> 4) & 1) * 16;
    const uint32_t b_row = (uint32_t)(nw + (lane & 7) + ((lane >> 4) & 1) * 8) * ROWB;
    const uint32_t b_col = ((lane >> 3) & 1) * 16;

    uint32_t ah[2][4][4], bh[2][4][4];   // fragment double buffers

    // Prologue: stages 0 and 1
    load_stage(sbase + 0 * STAGE_B, 0 * BK, m0, n0);
    load_stage(sbase + 1 * STAGE_B, 1 * BK, m0, n0);

    for (int kt = 0; kt < NKCH; kt++) {
        // ALL issued cp.async complete -> stages kt AND kt+1 both resident.
        asm volatile("cp.async.wait_group 0;" ::: "memory");
        __syncthreads();

        const uint32_t sb = sbase + (uint32_t)(kt % NSTAGE) * STAGE_B;
        const bool refill = (kt + 2 < NKCH);
        const uint32_t rb_stage = sbase + (uint32_t)((kt + 2) % NSTAGE) * STAGE_B;
        const int rk0 = (kt + 2) * BK;
        const uint32_t sbn = sbase + (uint32_t)((kt + 1) % NSTAGE) * STAGE_B;

        // kt=0 only: preload ks=0 fragments (later kts: prefetched at prev ks=3)
        if (kt == 0) {
#pragma unroll
            for (int mt = 0; mt < 4; mt++) {
                uint32_t ra = sb + OFF_AH + a_row + (uint32_t)(mt * 16) * ROWB + a_col;
                LDSM_X4(ah[0][mt][0], ah[0][mt][1], ah[0][mt][2], ah[0][mt][3], ra);
            }
#pragma unroll
            for (int nt = 0; nt < 4; nt++) {
                uint32_t rb = sb + OFF_BH + b_row + (uint32_t)(nt * 16) * ROWB + b_col;
                LDSM_X4(bh[0][nt][0], bh[0][nt][1], bh[0][nt][2], bh[0][nt][3], rb);
            }
        }

#pragma unroll
        for (int ks = 0; ks < NKS; ks++) {
            const int cur = ks & 1, nxt = cur ^ 1;
            // Prefetch next fragments: within-kt (ks<3) or next-kt ks=0 (ks==3)
            if (ks < NKS - 1) {
                const uint32_t kb = (uint32_t)(ks + 1) * 32;
#pragma unroll
                for (int mt = 0; mt < 4; mt++) {
                    uint32_t ra = sb + OFF_AH + a_row + (uint32_t)(mt * 16) * ROWB + kb + a_col;
                    LDSM_X4(ah[nxt][mt][0], ah[nxt][mt][1], ah[nxt][mt][2], ah[nxt][mt][3], ra);
                }
#pragma unroll
                for (int nt = 0; nt < 4; nt++) {
                    uint32_t rb = sb + OFF_BH + b_row + (uint32_t)(nt * 16) * ROWB + kb + b_col;
                    LDSM_X4(bh[nxt][nt][0], bh[nxt][nt][1], bh[nxt][nt][2], bh[nxt][nt][3], rb);
                }
            } else if (kt + 1 < NKCH) {
#pragma unroll
                for (int mt = 0; mt < 4; mt++) {
                    uint32_t ra = sbn + OFF_AH + a_row + (uint32_t)(mt * 16) * ROWB + a_col;
                    LDSM_X4(ah[nxt][mt][0], ah[nxt][mt][1], ah[nxt][mt][2], ah[nxt][mt][3], ra);
                }
#pragma unroll
                for (int nt = 0; nt < 4; nt++) {
                    uint32_t rb = sbn + OFF_BH + b_row + (uint32_t)(nt * 16) * ROWB + b_col;
                    LDSM_X4(bh[nxt][nt][0], bh[nxt][nt][1], bh[nxt][nt][2], bh[nxt][nt][3], rb);
                }
            }
            // Spread one refill chunk per ks
            if (refill) {
                load_chunk(rb_stage, rk0, m0, n0, ks);
                if (ks == NKS - 1) CP_COMMIT();
            }
            // MMAs for current ks
#pragma unroll
            for (int mt = 0; mt < 4; mt++) {
#pragma unroll
                for (int nt = 0; nt < 4; nt++) {
                    MMA16816(c[mt][2 * nt],     ah[cur][mt], bh[cur][nt][0], bh[cur][nt][1]);
                    MMA16816(c[mt][2 * nt + 1], ah[cur][mt], bh[cur][nt][2], bh[cur][nt][3]);
                }
            }
        }
    }

    // ----- Fused epilogue -----
    const int g = lane >> 2;
    const int tg = lane & 3;

    int   sid[4][2];
    float siv[4][2];
    int   lrow[4][2];
#pragma unroll
    for (int mt = 0; mt < 4; mt++) {
#pragma unroll
        for (int hf = 0; hf < 2; hf++) {
            const int l = ltile + mw + mt * 16 + g + hf * 8;
            lrow[mt][hf] = l;
            int found = -1;
#pragma unroll
            for (int s = 0; s < SS; s++) {
                if (l >= s_sp[2 * s] && l < s_sp[2 * s + 1]) found = s;
            }
            sid[mt][hf] = found;
            siv[mt][hf] = (found >= 0) ? s_inv[found] : 0.0f;
        }
    }

#pragma unroll
    for (int mt = 0; mt < 4; mt++) {
#pragma unroll
        for (int j = 0; j < 8; j++) {
            const int col = nw + j * 8 + tg * 2;
            const int ncol = n0 + col;
            const float b0 = s_bias[col];
            const float b1 = s_bias[col + 1];
            const float v00 = tanh_fast(c[mt][j][0] + b0);
            const float v01 = tanh_fast(c[mt][j][1] + b1);
            const float v10 = tanh_fast(c[mt][j][2] + b0);
            const float v11 = tanh_fast(c[mt][j][3] + b1);

            if (lrow[mt][0] == 0) {
                out[PASS_OFF + nidx * HH + ncol]     = v00;
                out[PASS_OFF + nidx * HH + ncol + 1] = v01;
            }
            if (sid[mt][0] >= 0) {
                float* dst = &out[SENT_OFF + (size_t)(nidx * SS + sid[mt][0]) * HH + ncol];
                atomicAdd(dst,     v00 * siv[mt][0]);
                atomicAdd(dst + 1, v01 * siv[mt][0]);
            }
            if (sid[mt][1] >= 0) {
                float* dst = &out[SENT_OFF + (size_t)(nidx * SS + sid[mt][1]) * HH + ncol];
                atomicAdd(dst,     v10 * siv[mt][1]);
                atomicAdd(dst + 1, v11 * siv[mt][1]);
            }
        }
    }
}

// ---------------------------------------------------------------------------
// Launch
// ---------------------------------------------------------------------------
extern "C" void kernel_launch(void* const* d_in, const int* in_sizes, int n_in,
                              void* d_out, int out_size) {
    const float* hs    = (const float*)d_in[0];
    const float* w     = (const float*)d_in[1];
    const float* b     = (const float*)d_in[2];
    const int*   spans = (const int*)d_in[4];
    float* out = (float*)d_out;

    cudaFuncSetAttribute(gemm_kernel,
                         cudaFuncAttributeMaxDynamicSharedMemorySize, DYN_SMEM);

    convert_init_kernel<<<XBLK + WBLK + OBLK, 256>>>(hs, w, out);

    dim3 grid(HH / BN, M_TOTAL / BM);     // (6, 256)
    gemm_kernel<<<grid, 128, DYN_SMEM>>>(b, spans, out);
}

// round 17
// speedup vs baseline: 1.1134x; 1.1134x over previous
#include <cuda_runtime.h>
#include <cuda_fp16.h>
#include <cstdint>

// ---------------------------------------------------------------------------
// Problem constants
// ---------------------------------------------------------------------------
#define NB 64
#define LL 512
#define SS 16
#define HH 768
#define M_TOTAL (NB * LL)          // 32768

#define PASS_OFF 0
#define SENT_OFF (NB * HH)
#define MASK_OFF (NB * HH + NB * SS * HH)
#define OUT_TOTAL (NB * HH + NB * SS * HH + NB * SS)   // 836608

// GEMM tiling: CTA 128x128, 4 warps of 64x64, BK=64, 3 stages
#define BM 128
#define BN 128
#define BK 64
#define NKCH (HH / BK)             // 12
#define NKS (BK / 16)              // 4 (even -> frag parity carries across kt)
#define ROWB 144                   // 64 halves (128B) padded to 144B
#define OFF_AH 0
#define OFF_BH (128 * ROWB)        // 18432
#define STAGE_B (2 * 128 * ROWB)   // 36864
#define NSTAGE 3
#define DYN_SMEM (NSTAGE * STAGE_B)   // 110592 -> 2 CTAs/SM (221KB)

// ---------------------------------------------------------------------------
// Device scratch
// ---------------------------------------------------------------------------
__device__ __half g_xh[(size_t)M_TOTAL * HH];      // 48 MB
__device__ __half g_wh[HH * HH];

// ---------------------------------------------------------------------------
// PTX helpers
// ---------------------------------------------------------------------------
__device__ __forceinline__ uint32_t smem_u32(const void* p) {
    uint32_t a;
    asm("{ .reg .u64 t; cvta.to.shared.u64 t, %1; cvt.u32.u64 %0, t; }"
        : "=r"(a) : "l"(p));
    return a;
}

__device__ __forceinline__ void cp16(uint32_t saddr, const void* g) {
    asm volatile("cp.async.cg.shared.global [%0], [%1], 16;"
                 :: "r"(saddr), "l"(g) : "memory");
}

#define CP_COMMIT() asm volatile("cp.async.commit_group;" ::: "memory")

#define LDSM_X4(r0, r1, r2, r3, addr) \
    asm volatile("ldmatrix.sync.aligned.m8n8.x4.shared.b16 {%0,%1,%2,%3}, [%4];" \
                 : "=r"(r0), "=r"(r1), "=r"(r2), "=r"(r3) : "r"(addr))

#define MMA16816(c, a, b0, b1) \
    asm volatile("mma.sync.aligned.m16n8k16.row.col.f32.f16.f16.f32 " \
                 "{%0,%1,%2,%3}, {%4,%5,%6,%7}, {%8,%9}, {%0,%1,%2,%3};" \
                 : "+f"((c)[0]), "+f"((c)[1]), "+f"((c)[2]), "+f"((c)[3]) \
                 : "r"((a)[0]), "r"((a)[1]), "r"((a)[2]), "r"((a)[3]), \
                   "r"(b0), "r"(b1))

__device__ __forceinline__ float tanh_fast(float x) {
    float y;
    asm("tanh.approx.f32 %0, %1;" : "=f"(y) : "f"(x));
    return y;
}

// ---------------------------------------------------------------------------
// convert_x (MLP=4) + convert_w + output zero-init, one launch
// ---------------------------------------------------------------------------
#define X4 ((size_t)M_TOTAL * HH / 4)          // 6291456 float4s
#define XBLK ((X4 + 1023) / 1024)              // 6144 blocks (4 float4/thread)
#define W4 ((size_t)HH * HH / 4)               // 147456
#define WBLK ((W4 + 255) / 256)                // 576
#define O4 (OUT_TOTAL / 4)                     // 209152
#define OBLK ((O4 + 255) / 256)                // 818

__global__ __launch_bounds__(256) void convert_init_kernel(
    const float* __restrict__ xsrc, const float* __restrict__ wsrc,
    float* __restrict__ out) {
    const size_t bx = blockIdx.x;
    if (bx < XBLK) {
        const size_t base = bx * 1024 + threadIdx.x;
        float4 v[4];
#pragma unroll
        for (int j = 0; j < 4; j++)
            v[j] = reinterpret_cast<const float4*>(xsrc)[base + j * 256];
#pragma unroll
        for (int j = 0; j < 4; j++) {
            const size_t i = base + j * 256;
            reinterpret_cast<__half2*>(g_xh)[2 * i] =
                __half2(__float2half_rn(v[j].x), __float2half_rn(v[j].y));
            reinterpret_cast<__half2*>(g_xh)[2 * i + 1] =
                __half2(__float2half_rn(v[j].z), __float2half_rn(v[j].w));
        }
    } else if (bx < XBLK + WBLK) {
        size_t i = (bx - XBLK) * 256 + threadIdx.x;
        if (i >= W4) return;
        float4 v = reinterpret_cast<const float4*>(wsrc)[i];
        reinterpret_cast<__half2*>(g_wh)[2 * i] =
            __half2(__float2half_rn(v.x), __float2half_rn(v.y));
        reinterpret_cast<__half2*>(g_wh)[2 * i + 1] =
            __half2(__float2half_rn(v.z), __float2half_rn(v.w));
    } else {
        size_t i = (bx - XBLK - WBLK) * 256 + threadIdx.x;
        if (i < O4)
            reinterpret_cast<float4*>(out)[i] = make_float4(0.f, 0.f, 0.f, 0.f);
    }
}

// ---------------------------------------------------------------------------
// GEMM + fused pooling epilogue. CTA 128x128, 4 warps 64x64, BK=64,
// 3-stage, spread refill, cross-kt fragment prefetch with mid-kt barrier.
// ---------------------------------------------------------------------------
__device__ __forceinline__ void load_chunk(uint32_t sb, int k0, int m0, int n0,
                                           int chunk) {
    const int t = threadIdx.x;
#pragma unroll
    for (int i = 2 * chunk; i < 2 * chunk + 2; i++) {
        int c = t + 128 * i;
        int row = c >> 3, ch = c & 7;
        uint32_t so = (uint32_t)(row * ROWB + ch * 16);
        cp16(sb + OFF_AH + so, g_xh + (size_t)(m0 + row) * HH + k0 + ch * 8);
        cp16(sb + OFF_BH + so, g_wh + (size_t)(n0 + row) * HH + k0 + ch * 8);
    }
}

__device__ __forceinline__ void load_stage(uint32_t sb, int k0, int m0, int n0) {
#pragma unroll
    for (int ch = 0; ch < 4; ch++) load_chunk(sb, k0, m0, n0, ch);
    CP_COMMIT();
}

__global__ __launch_bounds__(128, 2) void gemm_kernel(
    const float* __restrict__ bias,
    const int* __restrict__ spans,
    float* __restrict__ out)
{
    extern __shared__ char dsm[];
    __shared__ float s_bias[BN];
    __shared__ int   s_sp[SS * 2];
    __shared__ float s_inv[SS];

    const int tid = threadIdx.x;
    const int wid = tid >> 5;
    const int lane = tid & 31;
    const int m0 = blockIdx.y * BM;
    const int n0 = blockIdx.x * BN;
    const int nidx = m0 >> 9;
    const int ltile = m0 & 511;

    const int mw = (wid & 1) * 64;
    const int nw = (wid >> 1) * 64;

    const uint32_t sbase = smem_u32(dsm);

    s_bias[tid] = bias[n0 + tid];
    if (tid < SS * 2) s_sp[tid] = spans[nidx * SS * 2 + tid];
    if (tid >= 64 && tid < 64 + SS) {
        int s = tid - 64;
        int st = spans[(nidx * SS + s) * 2];
        int en = spans[(nidx * SS + s) * 2 + 1];
        s_inv[s] = 1.0f / (float)(en - st);
    }

    float c[4][8][4];
#pragma unroll
    for (int mt = 0; mt < 4; mt++)
#pragma unroll
        for (int j = 0; j < 8; j++)
#pragma unroll
            for (int r = 0; r < 4; r++) c[mt][j][r] = 0.0f;

    const uint32_t a_row = (uint32_t)(mw + (lane & 15)) * ROWB;
    const uint32_t a_col = ((lane >> 4) & 1) * 16;
    const uint32_t b_row = (uint32_t)(nw + (lane & 7) + ((lane >> 4) & 1) * 8) * ROWB;
    const uint32_t b_col = ((lane >> 3) & 1) * 16;

    uint32_t ah[2][4][4], bh[2][4][4];   // fragment double buffers

    // Prologue: stages 0 and 1; verify stage 0 and preload its ks=0 fragments.
    load_stage(sbase + 0 * STAGE_B, 0 * BK, m0, n0);
    load_stage(sbase + 1 * STAGE_B, 1 * BK, m0, n0);
    asm volatile("cp.async.wait_group 1;" ::: "memory");   // G0 (stage 0) done
    __syncthreads();
#pragma unroll
    for (int mt = 0; mt < 4; mt++) {
        uint32_t ra = sbase + OFF_AH + a_row + (uint32_t)(mt * 16) * ROWB + a_col;
        LDSM_X4(ah[0][mt][0], ah[0][mt][1], ah[0][mt][2], ah[0][mt][3], ra);
    }
#pragma unroll
    for (int nt = 0; nt < 4; nt++) {
        uint32_t rb = sbase + OFF_BH + b_row + (uint32_t)(nt * 16) * ROWB + b_col;
        LDSM_X4(bh[0][nt][0], bh[0][nt][1], bh[0][nt][2], bh[0][nt][3], rb);
    }

    for (int kt = 0; kt < NKCH; kt++) {
        // WAR barrier: all warps finished reading stage (kt-1)%3 before its
        // refill (issued below) overwrites it. (kt=0: prologue barrier above.)
        if (kt) __syncthreads();

        const uint32_t sb = sbase + (uint32_t)(kt % NSTAGE) * STAGE_B;
        const bool refill = (kt + 2 < NKCH);
        const uint32_t rb_stage = sbase + (uint32_t)((kt + 2) % NSTAGE) * STAGE_B;
        const int rk0 = (kt + 2) * BK;
        const uint32_t sbn = sbase + (uint32_t)((kt + 1) % NSTAGE) * STAGE_B;

        // ks = 0,1,2: within-kt fragment pipeline + spread refill chunk
#pragma unroll
        for (int ks = 0; ks < NKS - 1; ks++) {
            const int cur = ks & 1, nxt = cur ^ 1;
            const uint32_t kb = (uint32_t)(ks + 1) * 32;
#pragma unroll
            for (int mt = 0; mt < 4; mt++) {
                uint32_t ra = sb + OFF_AH + a_row + (uint32_t)(mt * 16) * ROWB + kb + a_col;
                LDSM_X4(ah[nxt][mt][0], ah[nxt][mt][1], ah[nxt][mt][2], ah[nxt][mt][3], ra);
            }
#pragma unroll
            for (int nt = 0; nt < 4; nt++) {
                uint32_t rb = sb + OFF_BH + b_row + (uint32_t)(nt * 16) * ROWB + kb + b_col;
                LDSM_X4(bh[nxt][nt][0], bh[nxt][nt][1], bh[nxt][nt][2], bh[nxt][nt][3], rb);
            }
            if (refill) load_chunk(rb_stage, rk0, m0, n0, ks);
#pragma unroll
            for (int mt = 0; mt < 4; mt++) {
#pragma unroll
                for (int nt = 0; nt < 4; nt++) {
                    MMA16816(c[mt][2 * nt],     ah[cur][mt], bh[cur][nt][0], bh[cur][nt][1]);
                    MMA16816(c[mt][2 * nt + 1], ah[cur][mt], bh[cur][nt][2], bh[cur][nt][3]);
                }
            }
        }

        // ks = 3: mid-kt barrier -> stage kt+1 resident+visible; prefetch its
        // ks=0 fragments (buffer 0, parity-correct); commit refill; MMA.
        if (kt + 1 < NKCH) {
            asm volatile("cp.async.wait_group 0;" ::: "memory");  // drain refill(kt+1)
            __syncthreads();
#pragma unroll
            for (int mt = 0; mt < 4; mt++) {
                uint32_t ra = sbn + OFF_AH + a_row + (uint32_t)(mt * 16) * ROWB + a_col;
                LDSM_X4(ah[0][mt][0], ah[0][mt][1], ah[0][mt][2], ah[0][mt][3], ra);
            }
#pragma unroll
            for (int nt = 0; nt < 4; nt++) {
                uint32_t rb = sbn + OFF_BH + b_row + (uint32_t)(nt * 16) * ROWB + b_col;
                LDSM_X4(bh[0][nt][0], bh[0][nt][1], bh[0][nt][2], bh[0][nt][3], rb);
            }
            if (refill) {
                load_chunk(rb_stage, rk0, m0, n0, 3);
                CP_COMMIT();
            }
        }
#pragma unroll
        for (int mt = 0; mt < 4; mt++) {
#pragma unroll
            for (int nt = 0; nt < 4; nt++) {
                MMA16816(c[mt][2 * nt],     ah[1][mt], bh[1][nt][0], bh[1][nt][1]);
                MMA16816(c[mt][2 * nt + 1], ah[1][mt], bh[1][nt][2], bh[1][nt][3]);
            }
        }
    }

    // ----- Fused epilogue -----
    const int g = lane >> 2;
    const int tg = lane & 3;

    int   sid[4][2];
    float siv[4][2];
    int   lrow[4][2];
#pragma unroll
    for (int mt = 0; mt < 4; mt++) {
#pragma unroll
        for (int hf = 0; hf < 2; hf++) {
            const int l = ltile + mw + mt * 16 + g + hf * 8;
            lrow[mt][hf] = l;
            int found = -1;
#pragma unroll
            for (int s = 0; s < SS; s++) {
                if (l >= s_sp[2 * s] && l < s_sp[2 * s + 1]) found = s;
            }
            sid[mt][hf] = found;
            siv[mt][hf] = (found >= 0) ? s_inv[found] : 0.0f;
        }
    }

#pragma unroll
    for (int mt = 0; mt < 4; mt++) {
#pragma unroll
        for (int j = 0; j < 8; j++) {
            const int col = nw + j * 8 + tg * 2;
            const int ncol = n0 + col;
            const float b0 = s_bias[col];
            const float b1 = s_bias[col + 1];
            const float v00 = tanh_fast(c[mt][j][0] + b0);
            const float v01 = tanh_fast(c[mt][j][1] + b1);
            const float v10 = tanh_fast(c[mt][j][2] + b0);
            const float v11 = tanh_fast(c[mt][j][3] + b1);

            if (lrow[mt][0] == 0) {
                out[PASS_OFF + nidx * HH + ncol]     = v00;
                out[PASS_OFF + nidx * HH + ncol + 1] = v01;
            }
            if (sid[mt][0] >= 0) {
                float* dst = &out[SENT_OFF + (size_t)(nidx * SS + sid[mt][0]) * HH + ncol];
                atomicAdd(dst,     v00 * siv[mt][0]);
                atomicAdd(dst + 1, v01 * siv[mt][0]);
            }
            if (sid[mt][1] >= 0) {
                float* dst = &out[SENT_OFF + (size_t)(nidx * SS + sid[mt][1]) * HH + ncol];
                atomicAdd(dst,     v10 * siv[mt][1]);
                atomicAdd(dst + 1, v11 * siv[mt][1]);
            }
        }
    }
}

// ---------------------------------------------------------------------------
// Launch
// ---------------------------------------------------------------------------
extern "C" void kernel_launch(void* const* d_in, const int* in_sizes, int n_in,
                              void* d_out, int out_size) {
    const float* hs    = (const float*)d_in[0];
    const float* w     = (const float*)d_in[1];
    const float* b     = (const float*)d_in[2];
    const int*   spans = (const int*)d_in[4];
    float* out = (float*)d_out;

    cudaFuncSetAttribute(gemm_kernel,
                         cudaFuncAttributeMaxDynamicSharedMemorySize, DYN_SMEM);

    convert_init_kernel<<<XBLK + WBLK + OBLK, 256>>>(hs, w, out);

    dim3 grid(HH / BN, M_TOTAL / BM);     // (6, 256)
    gemm_kernel<<<grid, 128, DYN_SMEM>>>(b, spans, out);
}